// round 8
// baseline (speedup 1.0000x reference)
#include <cuda_runtime.h>

typedef unsigned long long u64;

// Problem constants
#define NB     512
#define DIN    128
#define DH     256
#define DOUT   10
#define CCH    0

// Feature layout per sample: [h1(256) | d2(256) | x(128) | d1(256) | h2(256)]
#define OFF_H1 0
#define OFF_D2 256
#define OFF_X  512
#define OFF_D1 640
#define OFF_H2 896
#define FDIM   1152

#define GRP    8      // samples per feat block
#define KB     16     // gram k sub-chunk (double buffered)
#define RPAD   132    // padded smem row (floats)

// norm indices
#define NX  0
#define NH1 1
#define ND2 2
#define ND1 3
#define NH2 4

// Scratch
__device__ __align__(16) float g_feat[2 * NB * FDIM];   // 4.7 MB
__device__ float g_inv[2 * NB];
__device__ __align__(16) float g_scr[9 * NB * NB];      // 9.4 MB chunk grams
__device__ __align__(16) float g_w2t[DH * DH];          // W2 transposed

// ---- packed f32x2 helpers (Blackwell) ----
__device__ __forceinline__ u64 pack2(float lo, float hi) {
    u64 r; asm("mov.b64 %0, {%1, %2};" : "=l"(r) : "f"(lo), "f"(hi)); return r;
}
__device__ __forceinline__ float2 unpk2(u64 v) {
    float2 r; asm("mov.b64 {%0, %1}, %2;" : "=f"(r.x), "=f"(r.y) : "l"(v)); return r;
}
__device__ __forceinline__ void fma2(u64& d, u64 a, u64 b) {
    asm("fma.rn.f32x2 %0, %1, %2, %3;" : "=l"(d) : "l"(a), "l"(b), "l"(d));
}
__device__ __forceinline__ void add2(u64& d, u64 a) {
    asm("add.rn.f32x2 %0, %1, %2;" : "=l"(d) : "l"(d), "l"(a));
}

// ---------------------------------------------------------------------------
// Kernel 0: W2 transpose (g_w2t[j][i] = W2[i][j]). 64 blocks x 256 threads.
// ---------------------------------------------------------------------------
__global__ __launch_bounds__(256) void w2t_kernel(const float* __restrict__ W2)
{
    __shared__ float t[32][33];
    const int tx = threadIdx.x & 31;
    const int ty = threadIdx.x >> 5;
    const int x0 = blockIdx.x * 32;
    const int y0 = blockIdx.y * 32;
#pragma unroll
    for (int r = 0; r < 4; r++)
        t[ty + 8 * r][tx] = W2[(size_t)(y0 + ty + 8 * r) * DH + x0 + tx];
    __syncthreads();
#pragma unroll
    for (int r = 0; r < 4; r++)
        g_w2t[(size_t)(x0 + ty + 8 * r) * DH + y0 + tx] = t[tx][ty + 8 * r];
}

// ---------------------------------------------------------------------------
// Kernel 1: features, 8 samples/block, 512 threads, cp.async W streaming.
// 128 blocks. col j = tid&255, interleaved K-half kq = tid>>8.
// W1/W2/W2T are prefetched in 32x256-float chunks (32 KB), double-buffered.
// ---------------------------------------------------------------------------

// One GEMV phase: acc[4] += sum over this thread's k-set of W[k][j] * acts[k][*]
// Thread's k within chunk c: k = 32*c + 2*u + kq, u = 0..15.
__device__ __forceinline__ void phase_accum(
    const float* __restrict__ Wg, int NCH,
    float* __restrict__ wbuf, const float* __restrict__ acts,
    int j, int kq, int tid, u64* acc)
{
    // prefetch chunk 0
    {
        unsigned dst = (unsigned)__cvta_generic_to_shared(wbuf);
        const float4* src = (const float4*)Wg;
#pragma unroll
        for (int r = 0; r < 4; r++)
            asm volatile("cp.async.cg.shared.global [%0], [%1], 16;"
                :: "r"(dst + (unsigned)(tid + 512 * r) * 16u),
                   "l"(src + tid + 512 * r));
        asm volatile("cp.async.commit_group;");
    }
#pragma unroll 1
    for (int c = 0; c < NCH; c++) {
        if (c + 1 < NCH) {
            unsigned dst = (unsigned)__cvta_generic_to_shared(
                wbuf + ((c + 1) & 1) * 8192);
            const float4* src = (const float4*)(Wg + (size_t)(c + 1) * 8192);
#pragma unroll
            for (int r = 0; r < 4; r++)
                asm volatile("cp.async.cg.shared.global [%0], [%1], 16;"
                    :: "r"(dst + (unsigned)(tid + 512 * r) * 16u),
                       "l"(src + tid + 512 * r));
            asm volatile("cp.async.commit_group;");
            asm volatile("cp.async.wait_group 1;");
        } else {
            asm volatile("cp.async.wait_group 0;");
        }
        __syncthreads();

        const float* wb = wbuf + (c & 1) * 8192;
        const float* ab = acts + c * 32 * GRP;
#pragma unroll
        for (int u = 0; u < 16; u++) {
            const int kl = 2 * u + kq;
            const float w = wb[kl * 256 + j];
            const u64 w2 = pack2(w, w);
            const ulonglong2* ap = (const ulonglong2*)(ab + kl * GRP);
            const ulonglong2 a01 = ap[0];
            const ulonglong2 a23 = ap[1];
            fma2(acc[0], w2, a01.x); fma2(acc[1], w2, a01.y);
            fma2(acc[2], w2, a23.x); fma2(acc[3], w2, a23.y);
        }
        __syncthreads();
    }
}

__global__ __launch_bounds__(512, 1) void feat_kernel(
    const float* __restrict__ x1, const float* __restrict__ x2,
    const float* __restrict__ W1, const float* __restrict__ b1,
    const float* __restrict__ W2, const float* __restrict__ b2,
    const float* __restrict__ W3)
{
    extern __shared__ __align__(16) unsigned char dynsmem[];
    float* wbuf  = (float*)dynsmem;            // 2 x 8192 floats  (64 KB)
    float* xs_t  = wbuf + 16384;               // [128][8]          (4 KB)
    float* h1s_t = xs_t + DIN * GRP;           // [256][8]          (8 KB)
    float* d2s_t = h1s_t + DH * GRP;           // [256][8]          (8 KB)
    u64*  part2  = (u64*)(d2s_t + DH * GRP);   // [4][256]          (8 KB)
    float* nacc  = (float*)(part2 + 4 * DH);   // [8][8]

    const int tid  = threadIdx.x;
    const int lane = tid & 31;
    const int q0   = blockIdx.x * GRP;
    const int j    = tid & 255;
    const int kq   = tid >> 8;            // 0 or 1 (interleaved k split)

    if (tid < GRP * 8) nacc[tid] = 0.f;
    __syncthreads();   // nacc must be zeroed before any atomicAdd below

    // ---- load x (transposed to [k][s]) + x^2 norm + store x to g_feat ----
    {
        const int s = tid >> 6;           // 0..7, warp-uniform (64 thr/sample)
        const int i0 = (tid & 63) * 2;    // 2 elems per thread
        const int q = q0 + s;
        const float* xp = (q < NB) ? (x1 + (size_t)q * DIN)
                                   : (x2 + (size_t)(q - NB) * DIN);
        const float v0 = xp[i0], v1 = xp[i0 + 1];
        xs_t[i0 * GRP + s] = v0; xs_t[(i0 + 1) * GRP + s] = v1;
        g_feat[(size_t)q * FDIM + OFF_X + i0]     = v0;
        g_feat[(size_t)q * FDIM + OFF_X + i0 + 1] = v1;
        float ss = v0 * v0 + v1 * v1;
#pragma unroll
        for (int o = 16; o > 0; o >>= 1) ss += __shfl_xor_sync(~0u, ss, o);
        if (lane == 0) atomicAdd(&nacc[s * 8 + NX], ss);
    }
    __syncthreads();

    float h1v[GRP];                       // live for d1 (kq==0 threads)

    // ================= z1 / h1 =================
    {
        u64 acc[4] = {0, 0, 0, 0};
        phase_accum(W1, DIN / 32, wbuf, xs_t, j, kq, tid, acc);
        if (kq == 1) {
#pragma unroll
            for (int p = 0; p < 4; p++) part2[p * DH + j] = acc[p];
        }
        __syncthreads();
        if (kq == 0) {
            const float bj = b1[j];
#pragma unroll
            for (int p = 0; p < 4; p++) {
                add2(acc[p], part2[p * DH + j]);
                const float2 z = unpk2(acc[p]);
                h1v[2 * p + 0] = fmaxf(z.x + bj, 0.f);
                h1v[2 * p + 1] = fmaxf(z.y + bj, 0.f);
            }
            float v[GRP];
#pragma unroll
            for (int s = 0; s < GRP; s++) {
                h1s_t[j * GRP + s] = h1v[s];
                g_feat[(size_t)(q0 + s) * FDIM + OFF_H1 + j] = h1v[s];
                v[s] = h1v[s] * h1v[s];
            }
#pragma unroll
            for (int s = 0; s < GRP; s++)
#pragma unroll
                for (int o = 16; o > 0; o >>= 1)
                    v[s] += __shfl_xor_sync(~0u, v[s], o);
            if (lane == 0) {
#pragma unroll
                for (int s = 0; s < GRP; s++)
                    atomicAdd(&nacc[s * 8 + NH1], v[s]);
            }
        }
        __syncthreads();
    }

    // ================= z2 / h2 / d2 =================
    {
        u64 acc[4] = {0, 0, 0, 0};
        phase_accum(W2, DH / 32, wbuf, h1s_t, j, kq, tid, acc);
        if (kq == 1) {
#pragma unroll
            for (int p = 0; p < 4; p++) part2[p * DH + j] = acc[p];
        }
        __syncthreads();
        if (kq == 0) {
            const float bj  = b2[j];
            const float w3c = W3[j * DOUT + CCH];
            float h2v[GRP], d2v[GRP];
#pragma unroll
            for (int p = 0; p < 4; p++) {
                add2(acc[p], part2[p * DH + j]);
                const float2 z = unpk2(acc[p]);
                const float za = z.x + bj, zb = z.y + bj;
                h2v[2 * p + 0] = fmaxf(za, 0.f);
                h2v[2 * p + 1] = fmaxf(zb, 0.f);
                d2v[2 * p + 0] = (za > 0.f) ? w3c : 0.f;
                d2v[2 * p + 1] = (zb > 0.f) ? w3c : 0.f;
            }
            float vh[GRP], vd[GRP];
#pragma unroll
            for (int s = 0; s < GRP; s++) {
                d2s_t[j * GRP + s] = d2v[s];
                float* fr = g_feat + (size_t)(q0 + s) * FDIM;
                fr[OFF_H2 + j] = h2v[s];
                fr[OFF_D2 + j] = d2v[s];
                vh[s] = h2v[s] * h2v[s];
                vd[s] = d2v[s] * d2v[s];
            }
#pragma unroll
            for (int s = 0; s < GRP; s++)
#pragma unroll
                for (int o = 16; o > 0; o >>= 1) {
                    vh[s] += __shfl_xor_sync(~0u, vh[s], o);
                    vd[s] += __shfl_xor_sync(~0u, vd[s], o);
                }
            if (lane == 0) {
#pragma unroll
                for (int s = 0; s < GRP; s++) {
                    atomicAdd(&nacc[s * 8 + NH2], vh[s]);
                    atomicAdd(&nacc[s * 8 + ND2], vd[s]);
                }
            }
        }
        __syncthreads();
    }

    // ================= d1 = relu'(z1) . (W2 d2), via W2T in smem ==========
    {
        u64 acc[4] = {0, 0, 0, 0};
        phase_accum(g_w2t, DH / 32, wbuf, d2s_t, j, kq, tid, acc);
        if (kq == 1) {
#pragma unroll
            for (int p = 0; p < 4; p++) part2[p * DH + j] = acc[p];
        }
        __syncthreads();
        if (kq == 0) {
            float d1v[GRP];
#pragma unroll
            for (int p = 0; p < 4; p++) {
                add2(acc[p], part2[p * DH + j]);
                const float2 z = unpk2(acc[p]);
                d1v[2 * p + 0] = (h1v[2 * p + 0] > 0.f) ? z.x : 0.f;
                d1v[2 * p + 1] = (h1v[2 * p + 1] > 0.f) ? z.y : 0.f;
            }
            float v[GRP];
#pragma unroll
            for (int s = 0; s < GRP; s++) {
                g_feat[(size_t)(q0 + s) * FDIM + OFF_D1 + j] = d1v[s];
                v[s] = d1v[s] * d1v[s];
            }
#pragma unroll
            for (int s = 0; s < GRP; s++)
#pragma unroll
                for (int o = 16; o > 0; o >>= 1)
                    v[s] += __shfl_xor_sync(~0u, v[s], o);
            if (lane == 0) {
#pragma unroll
                for (int s = 0; s < GRP; s++)
                    atomicAdd(&nacc[s * 8 + ND1], v[s]);
            }
        }
        __syncthreads();
    }

    // ---- inverse norms ----
    if (tid < GRP) {
        const int s = tid;
        const float normsq = 1.f + nacc[s * 8 + NH2]
                           + (1.f + nacc[s * 8 + NH1]) * nacc[s * 8 + ND2]
                           + (1.f + nacc[s * 8 + NX])  * nacc[s * 8 + ND1];
        g_inv[q0 + s] = rsqrtf(normsq);
    }
}

// ---------------------------------------------------------------------------
// Kernel 2: split-K chunk grams, f32x2 accumulators over column pairs.
// Grid (16 tiles, 9 chunks) = 144 blocks, 256 threads, 8x8 per thread.
// ---------------------------------------------------------------------------
__global__ __launch_bounds__(256) void gram_kernel()
{
    __shared__ __align__(16) float As[2][KB][RPAD];
    __shared__ __align__(16) float Bs[2][KB][RPAD];

    const int tid   = threadIdx.x;
    const int tx    = tid & 15;
    const int ty    = tid >> 4;
    const int tile  = blockIdx.x;
    const int chunk = blockIdx.y;
    const int ti    = tile >> 2;
    const int tj    = tile & 3;

    const int arow0 = ti * 128;
    const int brow0 = NB + tj * 128;
    const int kbase = chunk * 128;

    const int e0r = tid >> 2,         e0f = tid & 3;
    const int e1r = (tid + 256) >> 2, e1f = (tid + 256) & 3;

    float4 pa0, pa1, pb0, pb1;

    auto load_stage = [&](int st) {
        const int kk = kbase + st * KB;
        pa0 = *(const float4*)(g_feat + (size_t)(arow0 + e0r) * FDIM + kk + e0f * 4);
        pa1 = *(const float4*)(g_feat + (size_t)(arow0 + e1r) * FDIM + kk + e1f * 4);
        pb0 = *(const float4*)(g_feat + (size_t)(brow0 + e0r) * FDIM + kk + e0f * 4);
        pb1 = *(const float4*)(g_feat + (size_t)(brow0 + e1r) * FDIM + kk + e1f * 4);
    };
    auto store_stage = [&](int b) {
        As[b][e0f * 4 + 0][e0r] = pa0.x; As[b][e0f * 4 + 1][e0r] = pa0.y;
        As[b][e0f * 4 + 2][e0r] = pa0.z; As[b][e0f * 4 + 3][e0r] = pa0.w;
        As[b][e1f * 4 + 0][e1r] = pa1.x; As[b][e1f * 4 + 1][e1r] = pa1.y;
        As[b][e1f * 4 + 2][e1r] = pa1.z; As[b][e1f * 4 + 3][e1r] = pa1.w;
        Bs[b][e0f * 4 + 0][e0r] = pb0.x; Bs[b][e0f * 4 + 1][e0r] = pb0.y;
        Bs[b][e0f * 4 + 2][e0r] = pb0.z; Bs[b][e0f * 4 + 3][e0r] = pb0.w;
        Bs[b][e1f * 4 + 0][e1r] = pb1.x; Bs[b][e1f * 4 + 1][e1r] = pb1.y;
        Bs[b][e1f * 4 + 2][e1r] = pb1.z; Bs[b][e1f * 4 + 3][e1r] = pb1.w;
    };

    u64 acc2[8][4];
#pragma unroll
    for (int i = 0; i < 8; i++)
#pragma unroll
        for (int p = 0; p < 4; p++) acc2[i][p] = 0ull;

    load_stage(0);
    store_stage(0);
    __syncthreads();

    const int NSTAGE = 128 / KB;
#pragma unroll 1
    for (int st = 0; st < NSTAGE; st++) {
        if (st < NSTAGE - 1) load_stage(st + 1);
        const int b = st & 1;
#pragma unroll
        for (int k = 0; k < KB; k++) {
            const float4 a0 = *(const float4*)&As[b][k][ty * 4];
            const float4 a1 = *(const float4*)&As[b][k][64 + ty * 4];
            const ulonglong2 b0 = *(const ulonglong2*)&Bs[b][k][tx * 4];
            const ulonglong2 b1 = *(const ulonglong2*)&Bs[b][k][64 + tx * 4];
            const u64 bv[4] = {b0.x, b0.y, b1.x, b1.y};
            const u64 ad[8] = {pack2(a0.x, a0.x), pack2(a0.y, a0.y),
                               pack2(a0.z, a0.z), pack2(a0.w, a0.w),
                               pack2(a1.x, a1.x), pack2(a1.y, a1.y),
                               pack2(a1.z, a1.z), pack2(a1.w, a1.w)};
#pragma unroll
            for (int i = 0; i < 8; i++)
#pragma unroll
                for (int p = 0; p < 4; p++)
                    fma2(acc2[i][p], ad[i], bv[p]);
        }
        if (st < NSTAGE - 1) store_stage(b ^ 1);
        __syncthreads();
    }

    float* scr = g_scr + (size_t)chunk * NB * NB;
#pragma unroll
    for (int ri = 0; ri < 2; ri++) {
#pragma unroll
        for (int r = 0; r < 4; r++) {
            const int i = ri * 4 + r;
            const int m = ti * 128 + ri * 64 + ty * 4 + r;
            float* rp = scr + (size_t)m * NB + tj * 128;
            ulonglong2 v0, v1;
            v0.x = acc2[i][0]; v0.y = acc2[i][1];
            v1.x = acc2[i][2]; v1.y = acc2[i][3];
            *(ulonglong2*)(rp + tx * 4)      = v0;
            *(ulonglong2*)(rp + 64 + tx * 4) = v1;
        }
    }
}

// ---------------------------------------------------------------------------
// Kernel 3: combine chunk grams + normalize.
// chunks: 0,1 -> h1 | 2,3 -> d2 | 4 -> x | 5,6 -> d1 | 7,8 -> h2
// ---------------------------------------------------------------------------
__global__ __launch_bounds__(256) void combine_kernel(float* __restrict__ out)
{
    const int gid = blockIdx.x * 256 + threadIdx.x;
    const int row = gid >> 7;
    const int c4  = gid & 127;

    const size_t off = (size_t)row * NB;
    float4 g[9];
#pragma unroll
    for (int c = 0; c < 9; c++)
        g[c] = ((const float4*)(g_scr + (size_t)c * NB * NB + off))[c4];

    const float  ia = g_inv[row];
    const float4 ib = *(const float4*)&g_inv[NB + c4 * 4];

    float4 r;
    r.x = (1.f + g[7].x + g[8].x + (1.f + g[0].x + g[1].x) * (g[2].x + g[3].x)
           + (1.f + g[4].x) * (g[5].x + g[6].x)) * ia * ib.x;
    r.y = (1.f + g[7].y + g[8].y + (1.f + g[0].y + g[1].y) * (g[2].y + g[3].y)
           + (1.f + g[4].y) * (g[5].y + g[6].y)) * ia * ib.y;
    r.z = (1.f + g[7].z + g[8].z + (1.f + g[0].z + g[1].z) * (g[2].z + g[3].z)
           + (1.f + g[4].z) * (g[5].z + g[6].z)) * ia * ib.z;
    r.w = (1.f + g[7].w + g[8].w + (1.f + g[0].w + g[1].w) * (g[2].w + g[3].w)
           + (1.f + g[4].w) * (g[5].w + g[6].w)) * ia * ib.w;

    ((float4*)(out + off))[c4] = r;
}

// ---------------------------------------------------------------------------
// inputs: x1, x2, W1, b1, W2, b2, W3, b3 ; output [512,512] float32
// ---------------------------------------------------------------------------
extern "C" void kernel_launch(void* const* d_in, const int* in_sizes, int n_in,
                              void* d_out, int out_size)
{
    const float* x1 = (const float*)d_in[0];
    const float* x2 = (const float*)d_in[1];
    const float* W1 = (const float*)d_in[2];
    const float* b1 = (const float*)d_in[3];
    const float* W2 = (const float*)d_in[4];
    const float* b2 = (const float*)d_in[5];
    const float* W3 = (const float*)d_in[6];
    float* out = (float*)d_out;

    const int FEAT_SMEM = 16384 * 4            // wbuf 64 KB
                        + DIN * GRP * 4        // xs_t
                        + DH * GRP * 4 * 2     // h1s_t, d2s_t
                        + 4 * DH * 8           // part2
                        + GRP * 8 * 4;         // nacc
    cudaFuncSetAttribute(feat_kernel,
                         cudaFuncAttributeMaxDynamicSharedMemorySize, FEAT_SMEM);

    w2t_kernel<<<dim3(8, 8), 256>>>(W2);
    feat_kernel<<<(2 * NB) / GRP, 512, FEAT_SMEM>>>(x1, x2, W1, b1, W2, b2, W3);
    gram_kernel<<<dim3(16, 9), 256>>>();
    combine_kernel<<<256, 256>>>(out);
}